// round 16
// baseline (speedup 1.0000x reference)
#include <cuda_runtime.h>

#define BB 2
#define CC 512
#define NSd 2048
#define NGd 2000
#define NV 300

// ---- output layout (floats), concatenated reference tuple ----
static constexpr size_t O_VS    = 0;                                   // (B,NS,300)
static constexpr size_t O_VPROT = O_VS    + (size_t)BB*NSd*NV;         // (B,NS,3,3)
static constexpr size_t O_SC    = O_VPROT + (size_t)BB*NSd*9;          // (B,NS,12,4)
static constexpr size_t O_WD    = O_SC    + (size_t)BB*NSd*48;         // (B,NS,12,4)
static constexpr size_t O_TROT  = O_WD    + (size_t)BB*NSd*48;         // (B,NS,3,3)
static constexpr size_t O_TSC   = O_TROT  + (size_t)BB*NSd*9;          // (B,NS,12,4)
static constexpr size_t O_TWD   = O_TSC   + (size_t)BB*NSd*48;         // (B,NS,12,4)
static constexpr size_t O_GN    = O_TWD   + (size_t)BB*NSd*48;         // (B,NS,300)
static constexpr size_t O_GP    = O_GN    + (size_t)BB*NSd*NV;         // (B,NS,3)

// ---- device scratch (no allocations allowed) ----
__device__ float g_views[NV*3];
__device__ int   g_view_inds[BB*NV];
__device__ float g_gvrot[BB*NV*9];
__device__ int   g_nn[BB*NSd];
__device__ int   g_topv[BB*NSd];
__device__ float g_tmp[(size_t)BB*CC*NSd];
__device__ float g_res[(size_t)BB*CC*NSd];
__device__ unsigned g_umax, g_umin;

// ---------------------------------------------------------------
__device__ __forceinline__ void make_rot(float tx_, float ty_, float tz_, float* m)
{
    float ax0 = tx_, ax1 = ty_, ax2 = tz_;
    float ay0 = -ax1, ay1 = ax0, ay2 = 0.f;
    float yn = sqrtf(ay0*ay0 + ay1*ay1 + ay2*ay2);
    if (yn == 0.f) { ay0 = 0.f; ay1 = 1.f; ay2 = 0.f; }
    float an = sqrtf(ax0*ax0 + ax1*ax1 + ax2*ax2);
    ax0 /= an; ax1 /= an; ax2 /= an;
    float an2 = sqrtf(ay0*ay0 + ay1*ay1 + ay2*ay2);
    ay0 /= an2; ay1 /= an2; ay2 /= an2;
    float az0 = ax1*ay2 - ax2*ay1;
    float az1 = ax2*ay0 - ax0*ay2;
    float az2 = ax0*ay1 - ax1*ay0;
    m[0]=ax0; m[1]=ay0; m[2]=az0;
    m[3]=ax1; m[4]=ay1; m[5]=az1;
    m[6]=ax2; m[7]=ay2; m[8]=az2;
}

// fused views + per-batch view kNN + gvrot (one block per batch)
__global__ void k_setup(const float* __restrict__ pose)
{
    __shared__ float sR[9];
    __shared__ float sVx[NV], sVy[NV], sVz[NV];
    __shared__ float sgx[NV], sgy[NV], sgz[NV], srr[NV];
    __shared__ float sVR[NV*9];
    int b = blockIdx.x, tid = threadIdx.x;
    if (tid < 9) sR[tid] = pose[b*12 + (tid/3)*4 + (tid%3)];
    if (tid < NV) {
        float fv = (float)tid;
        float Z = (2.f*fv + 1.f) / 300.f - 1.f;
        float r = sqrtf(fmaxf(1.f - Z*Z, 0.f));
        float ang = (6.2831853071795864769f * fv) * 0.61803398874989484820f;
        float X = r * cosf(ang);
        float Y = r * sinf(ang);
        sVx[tid]=X; sVy[tid]=Y; sVz[tid]=Z;
        if (b == 0) { g_views[tid*3+0]=X; g_views[tid*3+1]=Y; g_views[tid*3+2]=Z; }
        make_rot(-X, -Y, -Z, &sVR[tid*9]);
    }
    __syncthreads();
    if (tid < NV) {
        float vx = sVx[tid], vy = sVy[tid], vz = sVz[tid];
        float gx = sR[0]*vx + sR[1]*vy + sR[2]*vz;
        float gy = sR[3]*vx + sR[4]*vy + sR[5]*vz;
        float gz = sR[6]*vx + sR[7]*vy + sR[8]*vz;
        sgx[tid]=gx; sgy[tid]=gy; sgz[tid]=gz;
        srr[tid]=gx*gx + gy*gy + gz*gz;
    }
    __syncthreads();
    if (tid < NV) {
        float qx = sVx[tid], qy = sVy[tid], qz = sVz[tid];
        float qq = qx*qx + qy*qy + qz*qz;
        float best = 1e30f; int bi = 0;
        for (int u = 0; u < NV; u++) {
            float d = (qq + srr[u]) - 2.f*(qx*sgx[u] + qy*sgy[u] + qz*sgz[u]);
            if (d < best) { best = d; bi = u; }
        }
        g_view_inds[b*NV + tid] = bi;
        const float* VR = &sVR[bi*9];
        float* O = g_gvrot + (size_t)(b*NV + tid)*9;
#pragma unroll
        for (int i = 0; i < 3; i++)
#pragma unroll
            for (int j = 0; j < 3; j++)
                O[i*3+j] = sR[i*3+0]*VR[0+j] + sR[i*3+1]*VR[3+j] + sR[i*3+2]*VR[6+j];
    }
}

// ---------------- fused kNN: transform grasp points on the fly ----------------
__global__ void k_nn(const float* __restrict__ pc, const float* __restrict__ gp,
                     const float* __restrict__ pose, float* __restrict__ out)
{
    __shared__ float sx[256], sy[256], sz[256], sr[256];
    __shared__ float sP[12];
    int b = blockIdx.y;
    int n = blockIdx.x*256 + threadIdx.x;
    if (threadIdx.x < 12) sP[threadIdx.x] = pose[b*12 + threadIdx.x];
    __syncthreads();
    float qx = pc[((size_t)b*NSd + n)*3 + 0];
    float qy = pc[((size_t)b*NSd + n)*3 + 1];
    float qz = pc[((size_t)b*NSd + n)*3 + 2];
    float qq = qx*qx + qy*qy + qz*qz;
    float best = 1e30f; int bi = 0;
    for (int t0 = 0; t0 < NGd; t0 += 256) {
        int r = t0 + threadIdx.x;
        __syncthreads();
        if (r < NGd) {
            const float* P = gp + (size_t)(b*NGd + r)*3;
            float p0 = P[0], p1 = P[1], p2 = P[2];
            float x = sP[0]*p0 + sP[1]*p1 + sP[2]*p2  + sP[3];
            float y = sP[4]*p0 + sP[5]*p1 + sP[6]*p2  + sP[7];
            float z = sP[8]*p0 + sP[9]*p1 + sP[10]*p2 + sP[11];
            sx[threadIdx.x] = x; sy[threadIdx.x] = y; sz[threadIdx.x] = z;
            sr[threadIdx.x] = x*x + y*y + z*z;
        } else { sx[threadIdx.x] = 0.f; sy[threadIdx.x] = 0.f; sz[threadIdx.x] = 0.f; sr[threadIdx.x] = 1e30f; }
        __syncthreads();
        int cnt = min(256, NGd - t0);
        for (int j = 0; j < cnt; j++) {
            float d = (qq + sr[j]) - 2.f*(qx*sx[j] + qy*sy[j] + qz*sz[j]);
            if (d < best) { best = d; bi = t0 + j; }
        }
    }
    g_nn[b*NSd + n] = bi;
    {
        const float* P = gp + (size_t)(b*NGd + bi)*3;
        float p0 = P[0], p1 = P[1], p2 = P[2];
        out[O_GP + ((size_t)b*NSd + n)*3 + 0] = sP[0]*p0 + sP[1]*p1 + sP[2]*p2  + sP[3];
        out[O_GP + ((size_t)b*NSd + n)*3 + 1] = sP[4]*p0 + sP[5]*p1 + sP[6]*p2  + sP[7];
        out[O_GP + ((size_t)b*NSd + n)*3 + 2] = sP[8]*p0 + sP[9]*p1 + sP[10]*p2 + sP[11];
    }
}

// ---------------- 3xTF32 tensor-core GEMM machinery ----------------
__device__ __forceinline__ unsigned f2tf32(float x)
{
    unsigned u;
    asm("cvt.rna.tf32.f32 %0, %1;" : "=r"(u) : "f"(x));
    return u;
}

#define MMA_TF32(d, a0v, a1v, a2v, a3v, b0v, b1v) \
    asm volatile("mma.sync.aligned.m16n8k8.row.col.f32.tf32.tf32.f32 " \
        "{%0,%1,%2,%3}, {%4,%5,%6,%7}, {%8,%9}, {%0,%1,%2,%3};" \
        : "+f"(d[0]), "+f"(d[1]), "+f"(d[2]), "+f"(d[3]) \
        : "r"(a0v), "r"(a1v), "r"(a2v), "r"(a3v), "r"(b0v), "r"(b1v))

// shared mainloop body: fills As/Bs (W selected by functor), computes acc.
// Block 64x64, BK=8, 4 warps (2x2), warp tile 32x32, occ 4.
struct GemmCtx {
    int bm0, bn0, am, ak0, bk, bn4, mw0, nw0, qid, tig;
};

template<typename LoadA>
__device__ __forceinline__ void gemm_mainloop(
    const GemmCtx& cx, const float* __restrict__ Xb, LoadA loadA,
    unsigned (*As_hi)[8][72], unsigned (*As_lo)[8][72],
    unsigned (*Bs_hi)[8][72], unsigned (*Bs_lo)[8][72],
    float acc[2][4][4])
{
    constexpr int K = CC, N = NSd, BK = 8;
    float4 a4, b4;
    a4 = loadA(0);
    b4 = *(const float4*)&Xb[(size_t)cx.bk*N + cx.bn4];
    {
        float av[4] = {a4.x,a4.y,a4.z,a4.w};
#pragma unroll
        for (int j=0;j<4;j++){
            unsigned hi = f2tf32(av[j]);
            As_hi[0][cx.ak0+j][cx.am] = hi;
            As_lo[0][cx.ak0+j][cx.am] = f2tf32(av[j] - __uint_as_float(hi));
        }
        float bv[4] = {b4.x,b4.y,b4.z,b4.w};
        uint4 hi4, lo4;
        hi4.x = f2tf32(bv[0]); lo4.x = f2tf32(bv[0] - __uint_as_float(hi4.x));
        hi4.y = f2tf32(bv[1]); lo4.y = f2tf32(bv[1] - __uint_as_float(hi4.y));
        hi4.z = f2tf32(bv[2]); lo4.z = f2tf32(bv[2] - __uint_as_float(hi4.z));
        hi4.w = f2tf32(bv[3]); lo4.w = f2tf32(bv[3] - __uint_as_float(hi4.w));
        *(uint4*)&Bs_hi[0][cx.bk][cx.bn4] = hi4;
        *(uint4*)&Bs_lo[0][cx.bk][cx.bn4] = lo4;
    }
    __syncthreads();

    for (int ck = 0; ck < K/BK; ck++){
        const int buf = ck & 1;
        const bool more = (ck+1 < K/BK);
        if (more){
            int k0 = (ck+1)*BK;
            a4 = loadA(k0);
            b4 = *(const float4*)&Xb[(size_t)(k0+cx.bk)*N + cx.bn4];
        }
        unsigned bhi0[4], bhi1[4], blo0[4], blo1[4];
#pragma unroll
        for (int nj=0;nj<4;nj++){
            int nc = cx.nw0 + nj*8 + cx.qid;
            bhi0[nj] = Bs_hi[buf][cx.tig  ][nc];
            bhi1[nj] = Bs_hi[buf][cx.tig+4][nc];
            blo0[nj] = Bs_lo[buf][cx.tig  ][nc];
            blo1[nj] = Bs_lo[buf][cx.tig+4][nc];
        }
#pragma unroll
        for (int mi=0;mi<2;mi++){
            int mr = cx.mw0 + mi*16 + cx.qid;
            unsigned ah0 = As_hi[buf][cx.tig  ][mr  ];
            unsigned ah1 = As_hi[buf][cx.tig  ][mr+8];
            unsigned ah2 = As_hi[buf][cx.tig+4][mr  ];
            unsigned ah3 = As_hi[buf][cx.tig+4][mr+8];
            unsigned al0 = As_lo[buf][cx.tig  ][mr  ];
            unsigned al1 = As_lo[buf][cx.tig  ][mr+8];
            unsigned al2 = As_lo[buf][cx.tig+4][mr  ];
            unsigned al3 = As_lo[buf][cx.tig+4][mr+8];
#pragma unroll
            for (int nj=0;nj<4;nj++){
                MMA_TF32(acc[mi][nj], al0, al1, al2, al3, bhi0[nj], bhi1[nj]);
                MMA_TF32(acc[mi][nj], ah0, ah1, ah2, ah3, blo0[nj], blo1[nj]);
                MMA_TF32(acc[mi][nj], ah0, ah1, ah2, ah3, bhi0[nj], bhi1[nj]);
            }
        }
        if (more){
            const int nb = buf^1;
            float av[4] = {a4.x,a4.y,a4.z,a4.w};
#pragma unroll
            for (int j=0;j<4;j++){
                unsigned hi = f2tf32(av[j]);
                As_hi[nb][cx.ak0+j][cx.am] = hi;
                As_lo[nb][cx.ak0+j][cx.am] = f2tf32(av[j] - __uint_as_float(hi));
            }
            float bv[4] = {b4.x,b4.y,b4.z,b4.w};
            uint4 hi4, lo4;
            hi4.x = f2tf32(bv[0]); lo4.x = f2tf32(bv[0] - __uint_as_float(hi4.x));
            hi4.y = f2tf32(bv[1]); lo4.y = f2tf32(bv[1] - __uint_as_float(hi4.y));
            hi4.z = f2tf32(bv[2]); lo4.z = f2tf32(bv[2] - __uint_as_float(hi4.z));
            hi4.w = f2tf32(bv[3]); lo4.w = f2tf32(bv[3] - __uint_as_float(hi4.w));
            *(uint4*)&Bs_hi[nb][cx.bk][cx.bn4] = hi4;
            *(uint4*)&Bs_lo[nb][cx.bk][cx.bn4] = lo4;
        }
        __syncthreads();
    }
}

__device__ __forceinline__ GemmCtx make_ctx(int tid, int bm0, int bn0)
{
    GemmCtx cx;
    cx.bm0 = bm0; cx.bn0 = bn0;
    int warp = tid >> 5, lane = tid & 31;
    cx.mw0 = (warp >> 1)*32; cx.nw0 = (warp & 1)*32;
    cx.qid = lane >> 2; cx.tig = lane & 3;
    cx.am = tid >> 1; cx.ak0 = (tid & 1)*4;
    cx.bk = tid >> 4; cx.bn4 = (tid & 15)*4;
    return cx;
}

// MODE 0: plain Y=relu(WX+b) into M x N; MODE 2: sw2 scatter (M=96, guard)
template<int MODE,int RELU,bool GUARD>
__global__ __launch_bounds__(128,4) void k_gemm_tc(
    const float* __restrict__ W, const float* __restrict__ X,
    const float* __restrict__ bias, float* __restrict__ Y, int M)
{
    constexpr int K = CC, N = NSd;
    __shared__ unsigned As_hi[2][8][72];
    __shared__ unsigned As_lo[2][8][72];
    __shared__ unsigned Bs_hi[2][8][72];
    __shared__ unsigned Bs_lo[2][8][72];

    const int b = blockIdx.z;
    GemmCtx cx = make_ctx(threadIdx.x, blockIdx.y*64, blockIdx.x*64);
    const float* Xb = X + (size_t)b*K*N + cx.bn0;

    float acc[2][4][4];
#pragma unroll
    for (int i=0;i<2;i++)
#pragma unroll
        for (int j=0;j<4;j++)
#pragma unroll
            for (int r=0;r<4;r++) acc[i][j][r] = 0.f;

    const int gm = cx.bm0 + cx.am;
    auto loadA = [&](int k0) -> float4 {
        if (!GUARD || gm < M) return *(const float4*)&W[(size_t)gm*K + k0 + cx.ak0];
        return make_float4(0.f,0.f,0.f,0.f);
    };
    gemm_mainloop(cx, Xb, loadA, As_hi, As_lo, Bs_hi, Bs_lo, acc);

#pragma unroll
    for (int mi=0;mi<2;mi++){
        int r0 = cx.bm0 + cx.mw0 + mi*16 + cx.qid;
        int r1 = r0 + 8;
        float bv0 = (!GUARD || r0 < M) ? bias[r0] : 0.f;
        float bv1 = (!GUARD || r1 < M) ? bias[r1] : 0.f;
#pragma unroll
        for (int nj=0;nj<4;nj++){
            int c = cx.bn0 + cx.nw0 + nj*8 + 2*cx.tig;
            float v00 = acc[mi][nj][0] + bv0;
            float v01 = acc[mi][nj][1] + bv0;
            float v10 = acc[mi][nj][2] + bv1;
            float v11 = acc[mi][nj][3] + bv1;
            if (RELU){
                v00 = fmaxf(v00,0.f); v01 = fmaxf(v01,0.f);
                v10 = fmaxf(v10,0.f); v11 = fmaxf(v11,0.f);
            }
            if (MODE == 0){
                if (!GUARD || r0 < M)
                    *(float2*)&Y[((size_t)b*M + r0)*N + c] = make_float2(v00, v01);
                if (!GUARD || r1 < M)
                    *(float2*)&Y[((size_t)b*M + r1)*N + c] = make_float2(v10, v11);
            } else {
                if (!GUARD || r0 < M){
                    size_t base0 = (r0 < 48)
                        ? O_SC + ((size_t)b*NSd)*48 + r0
                        : O_WD + ((size_t)b*NSd)*48 + (r0 - 48);
                    Y[base0 + (size_t)c*48]     = v00;
                    Y[base0 + (size_t)(c+1)*48] = v01;
                }
                if (!GUARD || r1 < M){
                    size_t base1 = (r1 < 48)
                        ? O_SC + ((size_t)b*NSd)*48 + r1
                        : O_WD + ((size_t)b*NSd)*48 + (r1 - 48);
                    Y[base1 + (size_t)c*48]     = v10;
                    Y[base1 + (size_t)(c+1)*48] = v11;
                }
            }
        }
    }
}

// fused g3+sw1: rows [0,512) = sw1 (relu -> g_tmp), rows [512,812) = aw3 (-> O_VS scatter)
__global__ __launch_bounds__(128,4) void k_gemm_fused(
    const float* __restrict__ sw1w, const float* __restrict__ sw1b,
    const float* __restrict__ aw3w, const float* __restrict__ aw3b,
    const float* __restrict__ X, float* __restrict__ Ytmp, float* __restrict__ out)
{
    constexpr int K = CC, N = NSd, MT = 812;
    __shared__ unsigned As_hi[2][8][72];
    __shared__ unsigned As_lo[2][8][72];
    __shared__ unsigned Bs_hi[2][8][72];
    __shared__ unsigned Bs_lo[2][8][72];

    const int b = blockIdx.z;
    GemmCtx cx = make_ctx(threadIdx.x, blockIdx.y*64, blockIdx.x*64);
    const float* Xb = X + (size_t)b*K*N + cx.bn0;

    float acc[2][4][4];
#pragma unroll
    for (int i=0;i<2;i++)
#pragma unroll
        for (int j=0;j<4;j++)
#pragma unroll
            for (int r=0;r<4;r++) acc[i][j][r] = 0.f;

    const int gm = cx.bm0 + cx.am;
    auto loadA = [&](int k0) -> float4 {
        if (gm < 512)      return *(const float4*)&sw1w[(size_t)gm*K + k0 + cx.ak0];
        else if (gm < MT)  return *(const float4*)&aw3w[(size_t)(gm-512)*K + k0 + cx.ak0];
        return make_float4(0.f,0.f,0.f,0.f);
    };
    gemm_mainloop(cx, Xb, loadA, As_hi, As_lo, Bs_hi, Bs_lo, acc);

#pragma unroll
    for (int mi=0;mi<2;mi++){
        int rr[2]; rr[0] = cx.bm0 + cx.mw0 + mi*16 + cx.qid; rr[1] = rr[0] + 8;
#pragma unroll
        for (int h=0; h<2; h++){
            int r = rr[h];
            if (r >= MT) continue;
            float bv = (r < 512) ? sw1b[r] : aw3b[r-512];
#pragma unroll
            for (int nj=0;nj<4;nj++){
                int c = cx.bn0 + cx.nw0 + nj*8 + 2*cx.tig;
                float va = acc[mi][nj][2*h+0] + bv;
                float vb = acc[mi][nj][2*h+1] + bv;
                if (r < 512){
                    va = fmaxf(va, 0.f); vb = fmaxf(vb, 0.f);
                    *(float2*)&Ytmp[((size_t)b*512 + r)*N + c] = make_float2(va, vb);
                } else {
                    int m = r - 512;
                    out[O_VS + ((size_t)b*NSd + c  )*NV + m] = va;
                    out[O_VS + ((size_t)b*NSd + c+1)*NV + m] = vb;
                }
            }
        }
    }
}

// ---------------- argmax over views + vp_rot ----------------
__global__ void k_argmax(float* __restrict__ out)
{
    int g = (blockIdx.x * blockDim.x + threadIdx.x) >> 5;
    int lane = threadIdx.x & 31;
    if (g >= BB*NSd) return;
    const float* vs = out + O_VS + (size_t)g * NV;
    float best = -1e30f; int bi = 1 << 30;
    for (int v = lane; v < NV; v += 32) {
        float val = vs[v];
        if (val > best) { best = val; bi = v; }
    }
#pragma unroll
    for (int off = 16; off; off >>= 1) {
        float ob = __shfl_xor_sync(0xffffffffu, best, off);
        int   oi = __shfl_xor_sync(0xffffffffu, bi,  off);
        if (ob > best || (ob == best && oi < bi)) { best = ob; bi = oi; }
    }
    if (lane == 0) {
        g_topv[g] = bi;
        float m[9];
        make_rot(-g_views[bi*3], -g_views[bi*3+1], -g_views[bi*3+2], m);
        float* o = out + O_VPROT + (size_t)g*9;
#pragma unroll
        for (int i = 0; i < 9; i++) o[i] = m[i];
    }
}

__global__ void k_init_reduce()
{
    g_umax = 0u;
    g_umin = 0x7f800000u;
}

// ---------------- graspness (vectorized scan) ----------------
__global__ __launch_bounds__(256) void k_count(
    const float* __restrict__ gl, float* __restrict__ out)
{
    __shared__ float s_cnt[NV];
    __shared__ int   s_vi[NV];
    __shared__ float s_perm[NV];
    __shared__ float s_red[16];
    __shared__ float s_mx, s_mn;

    int idx = blockIdx.x;              // b*NSd + n
    int b = idx / NSd;
    int tid = threadIdx.x;
    int lane = tid & 31, w = tid >> 5;

    int nn = g_nn[idx];
    for (int v = tid; v < NV; v += 256) s_vi[v] = g_view_inds[b*NV + v];

    const float* row = gl + (size_t)(b*NGd + nn) * (NV*48);
    for (int u = w; u < NV; u += 8) {
        const float4* p4 = (const float4*)(row + u*48);
        unsigned c = 0;
        if (lane < 12) {
            float4 q = __ldg(p4 + lane);
            c = (unsigned)((q.x > 0.f) & (q.x <= 0.6f))
              + (unsigned)((q.y > 0.f) & (q.y <= 0.6f))
              + (unsigned)((q.z > 0.f) & (q.z <= 0.6f))
              + (unsigned)((q.w > 0.f) & (q.w <= 0.6f));
        }
        unsigned cnt = __reduce_add_sync(0xffffffffu, c);
        if (lane == 0) s_cnt[u] = (float)cnt;
    }
    __syncthreads();

    float lmx = -1e30f, lmn = 1e30f;
    for (int v = tid; v < NV; v += 256) {
        float gv = s_cnt[s_vi[v]] * (1.f/48.f);
        s_perm[v] = gv;
        lmx = fmaxf(lmx, gv); lmn = fminf(lmn, gv);
    }
#pragma unroll
    for (int off = 16; off; off >>= 1) {
        lmx = fmaxf(lmx, __shfl_xor_sync(0xffffffffu, lmx, off));
        lmn = fminf(lmn, __shfl_xor_sync(0xffffffffu, lmn, off));
    }
    if (lane == 0) { s_red[w] = lmx; s_red[8+w] = lmn; }
    __syncthreads();
    if (tid == 0) {
        float mx = -1e30f, mn = 1e30f;
        for (int i = 0; i < 8; i++) { mx = fmaxf(mx, s_red[i]); mn = fminf(mn, s_red[8+i]); }
        s_mx = mx; s_mn = mn;
    }
    __syncthreads();
    float mn = s_mn, den = s_mx - s_mn + 1e-8f;
    for (int v = tid; v < NV; v += 256)
        out[O_GN + (size_t)idx*NV + v] = (s_perm[v] - mn) / den;
}

// ---------------- top-view slice + rot + global reduce ----------------
__global__ void k_top(const float* __restrict__ gl, const float* __restrict__ gw,
                      float* __restrict__ out)
{
    __shared__ float s_top[48];
    int idx = blockIdx.x;
    int b = idx / NSd;
    int tid = threadIdx.x;
    int nn = g_nn[idx];
    int tv = g_topv[idx];
    int ut = g_view_inds[b*NV + tv];
    const float* rs = gl + (size_t)(b*NGd + nn)*(NV*48) + ut*48;
    const float* rw = gw + (size_t)(b*NGd + nn)*(NV*48) + ut*48;
    if (tid < 48) {
        float sc = __ldg(rs + tid);
        float wd = __ldg(rw + tid);
        bool lm = (sc > 0.f) & (wd <= 0.1f);
        float scv = lm ? sc : 0.f;
        out[O_TSC + (size_t)idx*48 + tid] = scv;
        out[O_TWD + (size_t)idx*48 + tid] = wd;
        s_top[tid] = scv;
    } else if (tid < 57) {
        out[O_TROT + (size_t)idx*9 + (tid - 48)] = g_gvrot[(size_t)(b*NV + tv)*9 + (tid - 48)];
    }
    __syncthreads();
    if (tid == 0) {
        float mx = 0.f, mnp = 1e30f; bool any = false;
        for (int i = 0; i < 48; i++) {
            float v = s_top[i];
            mx = fmaxf(mx, v);
            if (v > 0.f) { any = true; mnp = fminf(mnp, v); }
        }
        atomicMax(&g_umax, __float_as_uint(mx));
        if (any) atomicMin(&g_umin, __float_as_uint(mnp));
    }
}

__global__ void k_finalize(float* __restrict__ out)
{
    int i = blockIdx.x*blockDim.x + threadIdx.x;
    if (i >= BB*NSd*48) return;
    float v = out[O_TSC + i];
    if (v > 0.f) {
        float umax = __uint_as_float(g_umax);
        float umin = __uint_as_float(g_umin);
        out[O_TSC + i] = logf(umax / v) / (logf(umax / umin) + 1e-8f);
    }
}

// ---------------------------------------------------------------
extern "C" void kernel_launch(void* const* d_in, const int* in_sizes, int n_in,
                              void* d_out, int out_size)
{
    const float* seed  = (const float*)d_in[0];
    const float* pc    = (const float*)d_in[1];
    const float* pose  = (const float*)d_in[2];
    const float* gpts  = (const float*)d_in[3];
    const float* gl    = (const float*)d_in[4];
    const float* gw    = (const float*)d_in[5];
    const float* aw1w  = (const float*)d_in[6];
    const float* aw1b  = (const float*)d_in[7];
    const float* aw2w  = (const float*)d_in[8];
    const float* aw2b  = (const float*)d_in[9];
    const float* aw3w  = (const float*)d_in[10];
    const float* aw3b  = (const float*)d_in[11];
    const float* sw1w  = (const float*)d_in[12];
    const float* sw1b  = (const float*)d_in[13];
    const float* sw2w  = (const float*)d_in[14];
    const float* sw2b  = (const float*)d_in[15];
    float* out = (float*)d_out;

    static bool s_init = false;
    static cudaStream_t sA, sB;
    static cudaEvent_t e0, e2, eA, eB;
    static float *p_tmp = nullptr, *p_res = nullptr;
    if (!s_init) {
        cudaStreamCreateWithFlags(&sA, cudaStreamNonBlocking);
        cudaStreamCreateWithFlags(&sB, cudaStreamNonBlocking);
        cudaEventCreateWithFlags(&e0, cudaEventDisableTiming);
        cudaEventCreateWithFlags(&e2, cudaEventDisableTiming);
        cudaEventCreateWithFlags(&eA, cudaEventDisableTiming);
        cudaEventCreateWithFlags(&eB, cudaEventDisableTiming);
        cudaGetSymbolAddress((void**)&p_tmp, g_tmp);
        cudaGetSymbolAddress((void**)&p_res, g_res);
        s_init = true;
    }

    // origin: setup (submissions 1-2), fork e0
    k_init_reduce<<<1, 1>>>();
    k_setup<<<BB, 320>>>(pose);
    cudaEventRecord(e0, 0);

    // stream A (forked): nn (3)
    cudaStreamWaitEvent(sA, e0, 0);
    k_nn<<<dim3(NSd/256, BB), 256, 0, sA>>>(pc, gpts, pose, out);

    // origin: gemm1 = 4th submission (profiled)
    k_gemm_tc<0,1,false><<<dim3(32,8,BB), 128>>>(aw1w, seed,  aw1b, p_tmp, 512);

    // stream A: graspness scan (5)
    k_count<<<BB*NSd, 256, 0, sA>>>(gl, out);
    cudaEventRecord(eA, sA);

    // origin: gemm2 (6), fused g3+sw1 (7)
    k_gemm_tc<0,1,false><<<dim3(32,8,BB), 128>>>(aw2w, p_tmp, aw2b, p_res, 512);
    k_gemm_fused<<<dim3(32,13,BB), 128>>>(sw1w, sw1b, aw3w, aw3b, p_res, p_tmp, out);
    cudaEventRecord(e2, 0);

    // stream B (forked from e2): sw2 (8)
    cudaStreamWaitEvent(sB, e2, 0);
    k_gemm_tc<2,0,true><<<dim3(32,2,BB), 128, 0, sB>>>(sw2w, p_tmp, sw2b, out, 96);
    cudaEventRecord(eB, sB);

    // origin: argmax (9) concurrent with sw2
    k_argmax<<<(BB*NSd*32)/256, 256>>>(out);

    // join and finish
    cudaStreamWaitEvent((cudaStream_t)0, eA, 0);
    cudaStreamWaitEvent((cudaStream_t)0, eB, 0);
    k_top<<<BB*NSd, 64>>>(gl, gw, out);
    k_finalize<<<(BB*NSd*48 + 255)/256, 256>>>(out);
}